// round 16
// baseline (speedup 1.0000x reference)
#include <cuda_runtime.h>
#include <cuda_bf16.h>
#include <cuda_fp16.h>
#include <mma.h>
#include <math.h>
#include <stdint.h>

using namespace nvcuda;

// Problem constants
#define NN      100000
#define EMAX    1700000
#define NCLASS  40
#define SB      512
#define NB1     ((NN + SB - 1) / SB)
#define NTILE   782                    // ceil(NN/128)
#define NPAD    (NTILE * 128)          // 100096

// ---------------- scratch (static device globals) ----------------
__device__ __align__(16) __half g_Wh1h[(size_t)NPAD * 256];  // layer1 Wh fp16 (gather source)
__device__ __align__(16) __half g_Wh2h[(size_t)NPAD * 48];   // layer2 Wh fp16, ld=48
__device__ __align__(16) __half g_h16[(size_t)NPAD * 256];   // layer1 output fp16 (gemm2 A)
__device__ __align__(8)  __half g_w4[(size_t)EMAX * 4];      // per-edge weights (ex/64), 4 heads
__device__ float g_inv1[NN * 4];                             // per-node 64/denominator, 4 heads
__device__ float g_s1r[NN * 4];
__device__ float g_s1c[NN * 4];
__device__ float g_s2r[NN];
__device__ float g_s2c[NN];
__device__ int   g_deg[NN];
__device__ int   g_cur[NN];
__device__ int   g_off[NN + 1];
__device__ int   g_csr[EMAX];
__device__ int   g_bsum[256];
__device__ int   g_boff[256];
// operands
__device__ __align__(16) __half g_x16[(size_t)NPAD * 128];   // x fp16
__device__ __align__(16) __half g_B1f[128 * 256];            // B1 fp16 [k][n] ld 256
__device__ __align__(16) __half g_B2f[256 * 48];             // B2 fp16 [k][n] ld 48 (n>=40 zero)

// ---------------- helpers ----------------
__device__ __forceinline__ uint32_t smem_u32(const void* p) {
    uint32_t a;
    asm("{ .reg .u64 t; cvta.to.shared.u64 t, %1; cvt.u32.u64 %0, t; }" : "=r"(a) : "l"(p));
    return a;
}
__device__ __forceinline__ void cpa16(uint32_t dst, const void* src) {
    asm volatile("cp.async.cg.shared.global [%0], [%1], 16;" :: "r"(dst), "l"(src));
}
#define CP_COMMIT() asm volatile("cp.async.commit_group;" ::: "memory")
#define CP_WAIT1()  asm volatile("cp.async.wait_group 1;" ::: "memory")
#define CP_WAIT0()  asm volatile("cp.async.wait_group 0;" ::: "memory")

__device__ __forceinline__ float wmax(float v) {
    #pragma unroll
    for (int o = 16; o; o >>= 1) v = fmaxf(v, __shfl_xor_sync(0xffffffffu, v, o));
    return v;
}
__device__ __forceinline__ float wsum(float v) {
    #pragma unroll
    for (int o = 16; o; o >>= 1) v += __shfl_xor_sync(0xffffffffu, v, o);
    return v;
}
__device__ __forceinline__ float lrelu(float v) { return v > 0.f ? v : 0.1f * v; }
__device__ __forceinline__ float elu(float v)   { return v > 0.f ? v : expm1f(v); }

// ---------------- prep: x/B1/B2 -> fp16, zero h16 pad rows ----------------
#define XIT 3200000   // NN*128/4 float4 items
#define PB1 32768
#define PB2 12288
#define PZH 3072      // pad rows of g_h16: 96*256 halves = 3072 uint4
__global__ void k_prep(const float* __restrict__ x, const float* __restrict__ W,
                       const float* __restrict__ Wout) {
    int stride = gridDim.x * blockDim.x;
    for (int i = blockIdx.x * blockDim.x + threadIdx.x; i < XIT + PB1 + PB2 + PZH; i += stride) {
        if (i < XIT) {
            int r = i >> 5, kq = (i & 31) * 4;
            float4 v = __ldg((const float4*)&x[(size_t)r * 128 + kq]);
            __half2 p0 = __floats2half2_rn(v.x, v.y);
            __half2 p1 = __floats2half2_rn(v.z, v.w);
            uint2 o = make_uint2(*(uint32_t*)&p0, *(uint32_t*)&p1);
            *(uint2*)&g_x16[(size_t)r * 128 + kq] = o;
        } else if (i < XIT + PB1) {
            int i2 = i - XIT;
            int k = i2 >> 8, n = i2 & 255;
            float v = W[(n >> 6) * 8192 + k * 64 + (n & 63)];
            g_B1f[i2] = __float2half_rn(v);
        } else if (i < XIT + PB1 + PB2) {
            int j = i - XIT - PB1;
            int k = j / 48, n = j - k * 48;
            float v = (n < NCLASS) ? Wout[k * NCLASS + n] : 0.f;
            g_B2f[j] = __float2half_rn(v);
        } else {
            int j = i - XIT - PB1 - PB2;
            *(uint4*)((unsigned char*)g_h16 + (size_t)NN * 512 + (size_t)j * 16) =
                make_uint4(0, 0, 0, 0);
        }
    }
}

// ---------------- CSR build ----------------
__global__ void k_zero() {
    int i = blockIdx.x * blockDim.x + threadIdx.x;
    if (i < NN) { g_deg[i] = 0; g_cur[i] = 0; }
}
__global__ void k_count(const int* __restrict__ row, int E) {
    int e = blockIdx.x * blockDim.x + threadIdx.x;
    if (e < E) atomicAdd(&g_deg[__ldg(&row[e])], 1);
}
__global__ void k_scan1() {
    __shared__ int s[SB];
    int tid = threadIdx.x, g = blockIdx.x * SB + tid;
    int v = (g < NN) ? g_deg[g] : 0;
    s[tid] = v; __syncthreads();
    for (int o = 1; o < SB; o <<= 1) {
        int t = (tid >= o) ? s[tid - o] : 0;
        __syncthreads(); s[tid] += t; __syncthreads();
    }
    if (g < NN) g_off[g] = s[tid] - v;
    if (tid == SB - 1) g_bsum[blockIdx.x] = s[tid];
}
__global__ void k_scan2() {
    __shared__ int s[256];
    int tid = threadIdx.x;
    int v = (tid < NB1) ? g_bsum[tid] : 0;
    s[tid] = v; __syncthreads();
    for (int o = 1; o < 256; o <<= 1) {
        int t = (tid >= o) ? s[tid - o] : 0;
        __syncthreads(); s[tid] += t; __syncthreads();
    }
    g_boff[tid] = s[tid] - v;
}
__global__ void k_scan3(int E) {
    int tid = threadIdx.x, g = blockIdx.x * SB + tid;
    if (g < NN) g_off[g] += g_boff[blockIdx.x];
    if (g == 0) g_off[NN] = E;
}
__global__ void k_fill(const int* __restrict__ row, const int* __restrict__ col, int E) {
    int e = blockIdx.x * blockDim.x + threadIdx.x;
    if (e >= E) return;
    int r = __ldg(&row[e]);
    int p = g_off[r] + atomicAdd(&g_cur[r], 1);
    g_csr[p] = __ldg(&col[e]);
}

// ---------------- GEMM1: Wh1 = x @ B1 [128x128 CTA tile, K=128, 2 CTAs/SM, fused s1] ----------------
#define G1_STAGE 35840
#define G1_BOFF  18432
#define T1_BYTES 71680

__global__ __launch_bounds__(256, 2) void k_gemm1(const float* __restrict__ a) {
    extern __shared__ __align__(16) unsigned char smem[];
    uint32_t sbase = smem_u32(smem);
    int tid = threadIdx.x;
    int m0 = blockIdx.x * 128;
    int n0 = blockIdx.y * 128;

    #pragma unroll
    for (int c = 0; c < 2; c++) {
        uint32_t st = sbase + c * G1_STAGE;
        #pragma unroll
        for (int t = 0; t < 4; t++) {           // A: 1024 chunks (128 rows x 8)
            int idx = tid + t * 256;
            int r = idx >> 3, c8 = idx & 7;
            size_t so = ((size_t)(m0 + r) * 128 + c * 64 + c8 * 8) * 2;
            cpa16(st + (uint32_t)(r * 72 + c8 * 8) * 2, (const unsigned char*)g_x16 + so);
        }
        #pragma unroll
        for (int t = 0; t < 4; t++) {           // B: 1024 chunks (64 k-rows x 16)
            int idx = tid + t * 256;
            int kr = idx >> 4, c16 = idx & 15;
            size_t so = ((size_t)(c * 64 + kr) * 256 + n0 + c16 * 8) * 2;
            cpa16(st + G1_BOFF + (uint32_t)(kr * 136 + c16 * 8) * 2, (const unsigned char*)g_B1f + so);
        }
        CP_COMMIT();
    }

    int wid = tid >> 5, wm = wid & 3, wn = wid >> 2;  // 4M x 2N warps, tile 32x64

    wmma::fragment<wmma::accumulator, 16, 16, 16, float> acc[2][4];
    #pragma unroll
    for (int i = 0; i < 2; i++)
        #pragma unroll
        for (int j = 0; j < 4; j++) wmma::fill_fragment(acc[i][j], 0.f);

    CP_WAIT1();
    __syncthreads();

    #pragma unroll
    for (int c = 0; c < 2; c++) {
        const __half* A_ = (const __half*)(smem + c * G1_STAGE);
        const __half* B_ = (const __half*)(smem + c * G1_STAGE + G1_BOFF);
        #pragma unroll
        for (int k8 = 0; k8 < 4; k8++) {
            wmma::fragment<wmma::matrix_a, 16, 16, 16, __half, wmma::row_major> af[2];
            wmma::fragment<wmma::matrix_b, 16, 16, 16, __half, wmma::row_major> bfr[4];
            #pragma unroll
            for (int i = 0; i < 2; i++)
                wmma::load_matrix_sync(af[i], A_ + (wm * 32 + i * 16) * 72 + k8 * 16, 72);
            #pragma unroll
            for (int j = 0; j < 4; j++)
                wmma::load_matrix_sync(bfr[j], B_ + (k8 * 16) * 136 + wn * 64 + j * 16, 136);
            #pragma unroll
            for (int i = 0; i < 2; i++)
                #pragma unroll
                for (int j = 0; j < 4; j++)
                    wmma::mma_sync(acc[i][j], af[i], bfr[j], acc[i][j]);
        }
        if (c == 0) { CP_WAIT0(); __syncthreads(); }
    }

    // epilogue: fp32 tile ld 132 in smem, fp16 Wh1 write + fused s1
    __syncthreads();
    float* tile = (float*)smem;
    #pragma unroll
    for (int i = 0; i < 2; i++)
        #pragma unroll
        for (int j = 0; j < 4; j++)
            wmma::store_matrix_sync(&tile[(wm * 32 + i * 16) * 132 + wn * 64 + j * 16],
                                    acc[i][j], 132, wmma::mem_row_major);
    __syncthreads();

    #pragma unroll
    for (int t = 0; t < 8; t++) {
        int idx = tid + t * 256;
        int r = idx >> 4, c8 = (idx & 15) * 8;
        if (m0 + r < NN) {
            float4 v0 = *(const float4*)&tile[r * 132 + c8];
            float4 v1 = *(const float4*)&tile[r * 132 + c8 + 4];
            __half2 p0 = __floats2half2_rn(v0.x, v0.y);
            __half2 p1 = __floats2half2_rn(v0.z, v0.w);
            __half2 p2 = __floats2half2_rn(v1.x, v1.y);
            __half2 p3 = __floats2half2_rn(v1.z, v1.w);
            uint4 o = make_uint4(*(uint32_t*)&p0, *(uint32_t*)&p1,
                                 *(uint32_t*)&p2, *(uint32_t*)&p3);
            *(uint4*)&g_Wh1h[(size_t)(m0 + r) * 256 + n0 + c8] = o;
        }
    }
    {
        int hl = tid & 1;
        int row = tid >> 1;
        int hg = (n0 >> 6) + hl;
        const float* rp = &tile[row * 132 + hl * 64];
        float sr = 0.f, sc = 0.f;
        #pragma unroll
        for (int q = 0; q < 16; q++) {
            float4 v  = *(const float4*)&rp[q * 4];
            float4 ar = __ldg((const float4*)&a[hg * 128 + q * 4]);
            float4 ac = __ldg((const float4*)&a[hg * 128 + 64 + q * 4]);
            sr += v.x * ar.x + v.y * ar.y + v.z * ar.z + v.w * ar.w;
            sc += v.x * ac.x + v.y * ac.y + v.z * ac.z + v.w * ac.w;
        }
        int gr = m0 + row;
        if (gr < NN) {
            g_s1r[gr * 4 + hg] = sr;
            g_s1c[gr * 4 + hg] = sc;
        }
    }
}

// ---------------- GEMM2: Wh2 = h16 @ B2 [128x48, K=256, fp16 single-pass, fused s2] ----------------
#define T2_A 0
#define T2_B 34816
#define T2_STAGE 49152
#define T2_BYTES (2 * T2_STAGE)

__global__ __launch_bounds__(256) void k_gemm2(const float* __restrict__ aout) {
    extern __shared__ __align__(16) unsigned char smem[];
    uint32_t sbase = smem_u32(smem);
    int tid = threadIdx.x;
    int m0 = blockIdx.x * 128;

    #pragma unroll
    for (int c = 0; c < 2; c++) {
        uint32_t st = sbase + c * T2_STAGE;
        #pragma unroll
        for (int t = 0; t < 8; t++) {           // A: 2048 chunks (128 rows x 16)
            int idx = tid + t * 256;
            int r = idx >> 4, c16 = idx & 15;
            size_t so = ((size_t)(m0 + r) * 256 + c * 128 + c16 * 8) * 2;
            cpa16(st + T2_A + (uint32_t)(r * 136 + c16 * 8) * 2, (const unsigned char*)g_h16 + so);
        }
        #pragma unroll
        for (int t = 0; t < 3; t++) {           // B: 768 chunks (128 k-rows x 6)
            int idx = tid + t * 256;
            int kr = idx / 6, c6 = idx - kr * 6;
            size_t so = ((size_t)(c * 128 + kr) * 48 + c6 * 8) * 2;
            cpa16(st + T2_B + (uint32_t)(kr * 56 + c6 * 8) * 2, (const unsigned char*)g_B2f + so);
        }
        CP_COMMIT();
    }

    int wid = tid >> 5;                          // warp tile 16 x 48

    wmma::fragment<wmma::accumulator, 16, 16, 16, float> acc[3];
    #pragma unroll
    for (int j = 0; j < 3; j++) wmma::fill_fragment(acc[j], 0.f);

    CP_WAIT1();
    __syncthreads();

    #pragma unroll
    for (int c = 0; c < 2; c++) {
        const unsigned char* st = smem + c * T2_STAGE;
        const __half* A_ = (const __half*)(st + T2_A);
        const __half* B_ = (const __half*)(st + T2_B);
        #pragma unroll
        for (int k16 = 0; k16 < 8; k16++) {
            wmma::fragment<wmma::matrix_a, 16, 16, 16, __half, wmma::row_major> af;
            wmma::fragment<wmma::matrix_b, 16, 16, 16, __half, wmma::row_major> bfr[3];
            wmma::load_matrix_sync(af, A_ + (wid * 16) * 136 + k16 * 16, 136);
            #pragma unroll
            for (int j = 0; j < 3; j++)
                wmma::load_matrix_sync(bfr[j], B_ + (k16 * 16) * 56 + j * 16, 56);
            #pragma unroll
            for (int j = 0; j < 3; j++)
                wmma::mma_sync(acc[j], af, bfr[j], acc[j]);
        }
        if (c == 0) { CP_WAIT0(); __syncthreads(); }
    }

    __syncthreads();
    float* tile = (float*)smem;
    #pragma unroll
    for (int j = 0; j < 3; j++)
        wmma::store_matrix_sync(&tile[(wid * 16) * 56 + j * 16], acc[j], 56, wmma::mem_row_major);
    __syncthreads();

    #pragma unroll
    for (int t = 0; t < 6; t++) {               // fp16 Wh2 store
        int idx = tid + t * 256;
        int r = idx / 12, c4 = idx - r * 12;
        float4 v = *(const float4*)&tile[r * 56 + c4 * 4];
        __half2 p0 = __floats2half2_rn(v.x, v.y);
        __half2 p1 = __floats2half2_rn(v.z, v.w);
        uint2 o = make_uint2(*(uint32_t*)&p0, *(uint32_t*)&p1);
        *(uint2*)&g_Wh2h[(size_t)(m0 + r) * 48 + c4 * 4] = o;
    }
    if (tid < 128) {
        int row = tid;
        const float* rp = &tile[row * 56];
        float sr = 0.f, sc = 0.f;
        #pragma unroll
        for (int q = 0; q < 10; q++) {
            float4 v  = *(const float4*)&rp[q * 4];
            float4 ar = __ldg((const float4*)&aout[q * 4]);
            float4 ac = __ldg((const float4*)&aout[40 + q * 4]);
            sr += v.x * ar.x + v.y * ar.y + v.z * ar.z + v.w * ar.w;
            sc += v.x * ac.x + v.y * ac.y + v.z * ac.z + v.w * ac.w;
        }
        int gr = m0 + row;
        if (gr < NN) { g_s2r[gr] = sr; g_s2c[gr] = sc; }
    }
}

// ---------------- edge weights: lane-parallel exp + per-node inverse denominators ----------------
__global__ __launch_bounds__(256) void k_ew() {
    int gw = (blockIdx.x * blockDim.x + threadIdx.x) >> 5;
    int lane = threadIdx.x & 31;
    if (gw >= NN) return;
    const float4 sr = *(const float4*)&g_s1r[gw * 4];
    int beg = g_off[gw], end = g_off[gw + 1];
    float d0 = 0.f, d1 = 0.f, d2 = 0.f, d3 = 0.f;
    for (int e = beg + lane; e < end; e += 32) {
        int j = __ldg(&g_csr[e]);
        float4 s = __ldg((const float4*)&g_s1c[j * 4]);
        float e0 = __expf(lrelu(sr.x + s.x));
        float e1 = __expf(lrelu(sr.y + s.y));
        float e2 = __expf(lrelu(sr.z + s.z));
        float e3 = __expf(lrelu(sr.w + s.w));
        d0 += e0; d1 += e1; d2 += e2; d3 += e3;
        __half2 p01 = __floats2half2_rn(e0 * 0.015625f, e1 * 0.015625f);
        __half2 p23 = __floats2half2_rn(e2 * 0.015625f, e3 * 0.015625f);
        *(uint2*)&g_w4[(size_t)e * 4] = make_uint2(*(uint32_t*)&p01, *(uint32_t*)&p23);
    }
    d0 = wsum(d0); d1 = wsum(d1); d2 = wsum(d2); d3 = wsum(d3);
    if (lane == 0)
        *(float4*)&g_inv1[gw * 4] = make_float4(64.f / d0, 64.f / d1, 64.f / d2, 64.f / d3);
}

// ---------------- layer1 aggregation: flat loop, HFMA2, precomputed weights ----------------
__global__ __launch_bounds__(256) void k_gat1() {
    int gw = (blockIdx.x * blockDim.x + threadIdx.x) >> 5;
    int lane = threadIdx.x & 31;
    if (gw >= NN) return;
    int beg = g_off[gw], end = g_off[gw + 1];
    int hsel = lane >> 3;                         // head owned by this lane (8 cols each)

    __half2 accA0 = __float2half2_rn(0.f), accA1 = accA0, accA2 = accA0, accA3 = accA0;
    __half2 accB0 = accA0, accB1 = accA0, accB2 = accA0, accB3 = accA0;

    const __half* wbase = &g_w4[0];
    int e = beg;
    for (; e + 2 <= end; e += 2) {
        int jA = __ldg(&g_csr[e]);
        int jB = __ldg(&g_csr[e + 1]);
        __half wa = __ldg(wbase + (size_t)e * 4 + hsel);
        __half wb = __ldg(wbase + (size_t)(e + 1) * 4 + hsel);
        uint4 qA = __ldg((const uint4*)&g_Wh1h[(size_t)jA * 256 + 8 * lane]);
        uint4 qB = __ldg((const uint4*)&g_Wh1h[(size_t)jB * 256 + 8 * lane]);
        __half2 wtA = __half2half2(wa);
        __half2 wtB = __half2half2(wb);
        accA0 = __hfma2(wtA, *(__half2*)&qA.x, accA0);
        accA1 = __hfma2(wtA, *(__half2*)&qA.y, accA1);
        accA2 = __hfma2(wtA, *(__half2*)&qA.z, accA2);
        accA3 = __hfma2(wtA, *(__half2*)&qA.w, accA3);
        accB0 = __hfma2(wtB, *(__half2*)&qB.x, accB0);
        accB1 = __hfma2(wtB, *(__half2*)&qB.y, accB1);
        accB2 = __hfma2(wtB, *(__half2*)&qB.z, accB2);
        accB3 = __hfma2(wtB, *(__half2*)&qB.w, accB3);
    }
    if (e < end) {
        int jA = __ldg(&g_csr[e]);
        __half wa = __ldg(wbase + (size_t)e * 4 + hsel);
        uint4 qA = __ldg((const uint4*)&g_Wh1h[(size_t)jA * 256 + 8 * lane]);
        __half2 wtA = __half2half2(wa);
        accA0 = __hfma2(wtA, *(__half2*)&qA.x, accA0);
        accA1 = __hfma2(wtA, *(__half2*)&qA.y, accA1);
        accA2 = __hfma2(wtA, *(__half2*)&qA.z, accA2);
        accA3 = __hfma2(wtA, *(__half2*)&qA.w, accA3);
    }

    float4 inv4 = *(const float4*)&g_inv1[gw * 4];
    float inv = (hsel & 2) ? ((hsel & 1) ? inv4.w : inv4.z)
                           : ((hsel & 1) ? inv4.y : inv4.x);

    float2 fa0 = __half22float2(accA0), fb0 = __half22float2(accB0);
    float2 fa1 = __half22float2(accA1), fb1 = __half22float2(accB1);
    float2 fa2 = __half22float2(accA2), fb2 = __half22float2(accB2);
    float2 fa3 = __half22float2(accA3), fb3 = __half22float2(accB3);

    __half2 o0 = __floats2half2_rn(elu((fa0.x + fb0.x) * inv), elu((fa0.y + fb0.y) * inv));
    __half2 o1 = __floats2half2_rn(elu((fa1.x + fb1.x) * inv), elu((fa1.y + fb1.y) * inv));
    __half2 o2 = __floats2half2_rn(elu((fa2.x + fb2.x) * inv), elu((fa2.y + fb2.y) * inv));
    __half2 o3 = __floats2half2_rn(elu((fa3.x + fb3.x) * inv), elu((fa3.y + fb3.y) * inv));
    uint4 o = make_uint4(*(uint32_t*)&o0, *(uint32_t*)&o1,
                         *(uint32_t*)&o2, *(uint32_t*)&o3);
    *(uint4*)&g_h16[(size_t)gw * 256 + 8 * lane] = o;
}

// ---------------- layer2 attention + ELU + log_softmax (round-12 version) ----------------
__global__ void k_gat2(float* __restrict__ out) {
    int gw = (blockIdx.x * blockDim.x + threadIdx.x) >> 5;
    int lane = threadIdx.x & 31;
    if (gw >= NN) return;
    float s2v = __ldg(&g_s2r[gw]);
    int beg = g_off[gw], end = g_off[gw + 1];
    int half = lane >> 4, sl = lane & 15;

    float4 acc = make_float4(0.f, 0.f, 0.f, 0.f);
    float den = 0.f;
    for (int base = beg; base < end; base += 32) {
        int e = base + lane;
        int j = 0; float ex = 0.f;
        if (e < end) {
            j = __ldg(&g_csr[e]);
            ex = __expf(lrelu(s2v + __ldg(&g_s2c[j])));
            den += ex;
        }
        int cnt = min(32, end - base);
        for (int k = 0; k < cnt; k += 2) {
            int kk = k + half;
            int src = (kk < cnt) ? kk : k;
            int   jj = __shfl_sync(0xffffffffu, j,  src);
            float w  = __shfl_sync(0xffffffffu, ex, src);
            if (kk >= cnt) w = 0.f;
            if (sl < 10) {
                uint2 q = __ldg((const uint2*)&g_Wh2h[(size_t)jj * 48 + 4 * sl]);
                float2 f0 = __half22float2(*(__half2*)&q.x);
                float2 f1 = __half22float2(*(__half2*)&q.y);
                acc.x += w * f0.x; acc.y += w * f0.y; acc.z += w * f1.x; acc.w += w * f1.y;
            }
        }
    }
    acc.x += __shfl_xor_sync(0xffffffffu, acc.x, 16);
    acc.y += __shfl_xor_sync(0xffffffffu, acc.y, 16);
    acc.z += __shfl_xor_sync(0xffffffffu, acc.z, 16);
    acc.w += __shfl_xor_sync(0xffffffffu, acc.w, 16);
    den = wsum(den);
    float inv = 1.f / den;
    bool valid = (lane < 10);
    float o0 = -1e30f, o1 = -1e30f, o2 = -1e30f, o3 = -1e30f;
    if (valid) {
        o0 = elu(acc.x * inv); o1 = elu(acc.y * inv);
        o2 = elu(acc.z * inv); o3 = elu(acc.w * inv);
    }
    float mm = wmax(fmaxf(fmaxf(o0, o1), fmaxf(o2, o3)));
    float se = 0.f;
    if (valid) se = __expf(o0 - mm) + __expf(o1 - mm) + __expf(o2 - mm) + __expf(o3 - mm);
    se = wsum(se);
    float L = mm + logf(se);
    if (valid)
        *(float4*)&out[(size_t)gw * NCLASS + 4 * lane] = make_float4(o0 - L, o1 - L, o2 - L, o3 - L);
}

// ---------------- launch ----------------
extern "C" void kernel_launch(void* const* d_in, const int* in_sizes, int n_in,
                              void* d_out, int out_size) {
    const float* x    = (const float*)d_in[0];
    const float* W    = (const float*)d_in[1];
    const float* a    = (const float*)d_in[2];
    const float* Wout = (const float*)d_in[3];
    const float* aout = (const float*)d_in[4];
    const int*   row  = (const int*)d_in[5];
    const int*   col  = (const int*)d_in[6];
    int E = in_sizes[5];
    float* out = (float*)d_out;

    static cudaStream_t s2 = nullptr;
    static cudaEvent_t evF = nullptr, evJ = nullptr;
    if (!s2) {
        cudaStreamCreateWithFlags(&s2, cudaStreamNonBlocking);
        cudaEventCreateWithFlags(&evF, cudaEventDisableTiming);
        cudaEventCreateWithFlags(&evJ, cudaEventDisableTiming);
        cudaFuncSetAttribute(k_gemm1, cudaFuncAttributeMaxDynamicSharedMemorySize, T1_BYTES);
        cudaFuncSetAttribute(k_gemm2, cudaFuncAttributeMaxDynamicSharedMemorySize, T2_BYTES);
    }

    // fork CSR chain immediately
    cudaEventRecord(evF, 0);
    cudaStreamWaitEvent(s2, evF, 0);
    k_zero <<<(NN + 255) / 256, 256, 0, s2>>>();
    k_count<<<(E + 255) / 256, 256, 0, s2>>>(row, E);

    k_prep<<<1280, 256>>>(x, W, Wout);
    k_gemm1<<<dim3(NTILE, 2), 256, T1_BYTES>>>(a);     // profiled slot

    k_scan1<<<NB1, SB, 0, s2>>>();
    k_scan2<<<1, 256, 0, s2>>>();
    k_scan3<<<NB1, SB, 0, s2>>>(E);
    k_fill <<<(E + 255) / 256, 256, 0, s2>>>(row, col, E);

    cudaEventRecord(evJ, s2);
    cudaStreamWaitEvent(0, evJ, 0);

    k_ew  <<<(NN + 7) / 8, 256>>>();
    k_gat1<<<(NN + 7) / 8, 256>>>();
    k_gemm2<<<NTILE, 256, T2_BYTES>>>(aout);
    k_gat2<<<(NN + 7) / 8, 256>>>(out);
}

// round 17
// speedup vs baseline: 1.0634x; 1.0634x over previous
#include <cuda_runtime.h>
#include <cuda_bf16.h>
#include <cuda_fp16.h>
#include <mma.h>
#include <math.h>
#include <stdint.h>

using namespace nvcuda;

// Problem constants
#define NN      100000
#define EMAX    1700000
#define NCLASS  40
#define SB      512
#define NB1     ((NN + SB - 1) / SB)
#define NTILE   782                    // ceil(NN/128)
#define NPAD    (NTILE * 128)          // 100096

// ---------------- scratch (static device globals) ----------------
__device__ __align__(16) __half g_Wh1h[(size_t)NPAD * 256];  // layer1 Wh fp16 (gather source)
__device__ __align__(16) __half g_Wh2h[(size_t)NPAD * 48];   // layer2 Wh fp16, ld=48
__device__ __align__(16) __half g_h16[(size_t)NPAD * 256];   // layer1 output fp16 (gemm2 A)
__device__ float g_s1r[NN * 4];
__device__ float g_s1c[NN * 4];
__device__ float g_s2r[NN];
__device__ float g_s2c[NN];
__device__ int   g_deg[NN];
__device__ int   g_cur[NN];
__device__ int   g_off[NN + 1];
__device__ int   g_csr[EMAX];
__device__ int   g_bsum[256];
__device__ int   g_boff[256];
// operands
__device__ __align__(16) __half g_x16[(size_t)NPAD * 128];   // x fp16
__device__ __align__(16) __half g_B1f[128 * 256];            // B1 fp16 [k][n] ld 256
__device__ __align__(16) __half g_B2f[256 * 48];             // B2 fp16 [k][n] ld 48 (n>=40 zero)

// ---------------- helpers ----------------
__device__ __forceinline__ uint32_t smem_u32(const void* p) {
    uint32_t a;
    asm("{ .reg .u64 t; cvta.to.shared.u64 t, %1; cvt.u32.u64 %0, t; }" : "=r"(a) : "l"(p));
    return a;
}
__device__ __forceinline__ void cpa16(uint32_t dst, const void* src) {
    asm volatile("cp.async.cg.shared.global [%0], [%1], 16;" :: "r"(dst), "l"(src));
}
#define CP_COMMIT() asm volatile("cp.async.commit_group;" ::: "memory")
#define CP_WAIT1()  asm volatile("cp.async.wait_group 1;" ::: "memory")
#define CP_WAIT0()  asm volatile("cp.async.wait_group 0;" ::: "memory")

__device__ __forceinline__ float wmax(float v) {
    #pragma unroll
    for (int o = 16; o; o >>= 1) v = fmaxf(v, __shfl_xor_sync(0xffffffffu, v, o));
    return v;
}
__device__ __forceinline__ float wsum(float v) {
    #pragma unroll
    for (int o = 16; o; o >>= 1) v += __shfl_xor_sync(0xffffffffu, v, o);
    return v;
}
__device__ __forceinline__ float lrelu(float v) { return v > 0.f ? v : 0.1f * v; }
__device__ __forceinline__ float elu(float v)   { return v > 0.f ? v : expm1f(v); }

// ---------------- prep: x/B1/B2 -> fp16, zero h16 pad rows ----------------
#define XIT 3200000   // NN*128/4 float4 items
#define PB1 32768
#define PB2 12288
#define PZH 3072      // pad rows of g_h16: 96*256 halves = 3072 uint4
__global__ void k_prep(const float* __restrict__ x, const float* __restrict__ W,
                       const float* __restrict__ Wout) {
    int stride = gridDim.x * blockDim.x;
    for (int i = blockIdx.x * blockDim.x + threadIdx.x; i < XIT + PB1 + PB2 + PZH; i += stride) {
        if (i < XIT) {
            int r = i >> 5, kq = (i & 31) * 4;
            float4 v = __ldg((const float4*)&x[(size_t)r * 128 + kq]);
            __half2 p0 = __floats2half2_rn(v.x, v.y);
            __half2 p1 = __floats2half2_rn(v.z, v.w);
            uint2 o = make_uint2(*(uint32_t*)&p0, *(uint32_t*)&p1);
            *(uint2*)&g_x16[(size_t)r * 128 + kq] = o;
        } else if (i < XIT + PB1) {
            int i2 = i - XIT;
            int k = i2 >> 8, n = i2 & 255;
            float v = W[(n >> 6) * 8192 + k * 64 + (n & 63)];
            g_B1f[i2] = __float2half_rn(v);
        } else if (i < XIT + PB1 + PB2) {
            int j = i - XIT - PB1;
            int k = j / 48, n = j - k * 48;
            float v = (n < NCLASS) ? Wout[k * NCLASS + n] : 0.f;
            g_B2f[j] = __float2half_rn(v);
        } else {
            int j = i - XIT - PB1 - PB2;
            *(uint4*)((unsigned char*)g_h16 + (size_t)NN * 512 + (size_t)j * 16) =
                make_uint4(0, 0, 0, 0);
        }
    }
}

// ---------------- CSR build ----------------
__global__ void k_zero() {
    int i = blockIdx.x * blockDim.x + threadIdx.x;
    if (i < NN) { g_deg[i] = 0; g_cur[i] = 0; }
}
__global__ void k_count(const int* __restrict__ row, int E) {
    int e = blockIdx.x * blockDim.x + threadIdx.x;
    if (e < E) atomicAdd(&g_deg[__ldg(&row[e])], 1);
}
__global__ void k_scan1() {
    __shared__ int s[SB];
    int tid = threadIdx.x, g = blockIdx.x * SB + tid;
    int v = (g < NN) ? g_deg[g] : 0;
    s[tid] = v; __syncthreads();
    for (int o = 1; o < SB; o <<= 1) {
        int t = (tid >= o) ? s[tid - o] : 0;
        __syncthreads(); s[tid] += t; __syncthreads();
    }
    if (g < NN) g_off[g] = s[tid] - v;
    if (tid == SB - 1) g_bsum[blockIdx.x] = s[tid];
}
__global__ void k_scan2() {
    __shared__ int s[256];
    int tid = threadIdx.x;
    int v = (tid < NB1) ? g_bsum[tid] : 0;
    s[tid] = v; __syncthreads();
    for (int o = 1; o < 256; o <<= 1) {
        int t = (tid >= o) ? s[tid - o] : 0;
        __syncthreads(); s[tid] += t; __syncthreads();
    }
    g_boff[tid] = s[tid] - v;
}
__global__ void k_scan3(int E) {
    int tid = threadIdx.x, g = blockIdx.x * SB + tid;
    if (g < NN) g_off[g] += g_boff[blockIdx.x];
    if (g == 0) g_off[NN] = E;
}
__global__ void k_fill(const int* __restrict__ row, const int* __restrict__ col, int E) {
    int e = blockIdx.x * blockDim.x + threadIdx.x;
    if (e >= E) return;
    int r = __ldg(&row[e]);
    int p = g_off[r] + atomicAdd(&g_cur[r], 1);
    g_csr[p] = __ldg(&col[e]);
}

// ---------------- GEMM1: Wh1 = x @ B1 [128x128 CTA tile, K=128, 2 CTAs/SM, fused s1] ----------------
#define G1_STAGE 35840
#define G1_BOFF  18432
#define T1_BYTES 71680

__global__ __launch_bounds__(256, 2) void k_gemm1(const float* __restrict__ a) {
    extern __shared__ __align__(16) unsigned char smem[];
    uint32_t sbase = smem_u32(smem);
    int tid = threadIdx.x;
    int m0 = blockIdx.x * 128;
    int n0 = blockIdx.y * 128;

    #pragma unroll
    for (int c = 0; c < 2; c++) {
        uint32_t st = sbase + c * G1_STAGE;
        #pragma unroll
        for (int t = 0; t < 4; t++) {           // A: 1024 chunks (128 rows x 8)
            int idx = tid + t * 256;
            int r = idx >> 3, c8 = idx & 7;
            size_t so = ((size_t)(m0 + r) * 128 + c * 64 + c8 * 8) * 2;
            cpa16(st + (uint32_t)(r * 72 + c8 * 8) * 2, (const unsigned char*)g_x16 + so);
        }
        #pragma unroll
        for (int t = 0; t < 4; t++) {           // B: 1024 chunks (64 k-rows x 16)
            int idx = tid + t * 256;
            int kr = idx >> 4, c16 = idx & 15;
            size_t so = ((size_t)(c * 64 + kr) * 256 + n0 + c16 * 8) * 2;
            cpa16(st + G1_BOFF + (uint32_t)(kr * 136 + c16 * 8) * 2, (const unsigned char*)g_B1f + so);
        }
        CP_COMMIT();
    }

    int wid = tid >> 5, wm = wid & 3, wn = wid >> 2;  // 4M x 2N warps, tile 32x64

    wmma::fragment<wmma::accumulator, 16, 16, 16, float> acc[2][4];
    #pragma unroll
    for (int i = 0; i < 2; i++)
        #pragma unroll
        for (int j = 0; j < 4; j++) wmma::fill_fragment(acc[i][j], 0.f);

    CP_WAIT1();
    __syncthreads();

    #pragma unroll
    for (int c = 0; c < 2; c++) {
        const __half* A_ = (const __half*)(smem + c * G1_STAGE);
        const __half* B_ = (const __half*)(smem + c * G1_STAGE + G1_BOFF);
        #pragma unroll
        for (int k8 = 0; k8 < 4; k8++) {
            wmma::fragment<wmma::matrix_a, 16, 16, 16, __half, wmma::row_major> af[2];
            wmma::fragment<wmma::matrix_b, 16, 16, 16, __half, wmma::row_major> bfr[4];
            #pragma unroll
            for (int i = 0; i < 2; i++)
                wmma::load_matrix_sync(af[i], A_ + (wm * 32 + i * 16) * 72 + k8 * 16, 72);
            #pragma unroll
            for (int j = 0; j < 4; j++)
                wmma::load_matrix_sync(bfr[j], B_ + (k8 * 16) * 136 + wn * 64 + j * 16, 136);
            #pragma unroll
            for (int i = 0; i < 2; i++)
                #pragma unroll
                for (int j = 0; j < 4; j++)
                    wmma::mma_sync(acc[i][j], af[i], bfr[j], acc[i][j]);
        }
        if (c == 0) { CP_WAIT0(); __syncthreads(); }
    }

    // epilogue: fp32 tile ld 132 in smem, fp16 Wh1 write + fused s1
    __syncthreads();
    float* tile = (float*)smem;
    #pragma unroll
    for (int i = 0; i < 2; i++)
        #pragma unroll
        for (int j = 0; j < 4; j++)
            wmma::store_matrix_sync(&tile[(wm * 32 + i * 16) * 132 + wn * 64 + j * 16],
                                    acc[i][j], 132, wmma::mem_row_major);
    __syncthreads();

    #pragma unroll
    for (int t = 0; t < 8; t++) {
        int idx = tid + t * 256;
        int r = idx >> 4, c8 = (idx & 15) * 8;
        if (m0 + r < NN) {
            float4 v0 = *(const float4*)&tile[r * 132 + c8];
            float4 v1 = *(const float4*)&tile[r * 132 + c8 + 4];
            __half2 p0 = __floats2half2_rn(v0.x, v0.y);
            __half2 p1 = __floats2half2_rn(v0.z, v0.w);
            __half2 p2 = __floats2half2_rn(v1.x, v1.y);
            __half2 p3 = __floats2half2_rn(v1.z, v1.w);
            uint4 o = make_uint4(*(uint32_t*)&p0, *(uint32_t*)&p1,
                                 *(uint32_t*)&p2, *(uint32_t*)&p3);
            *(uint4*)&g_Wh1h[(size_t)(m0 + r) * 256 + n0 + c8] = o;
        }
    }
    {
        int hl = tid & 1;
        int row = tid >> 1;
        int hg = (n0 >> 6) + hl;
        const float* rp = &tile[row * 132 + hl * 64];
        float sr = 0.f, sc = 0.f;
        #pragma unroll
        for (int q = 0; q < 16; q++) {
            float4 v  = *(const float4*)&rp[q * 4];
            float4 ar = __ldg((const float4*)&a[hg * 128 + q * 4]);
            float4 ac = __ldg((const float4*)&a[hg * 128 + 64 + q * 4]);
            sr += v.x * ar.x + v.y * ar.y + v.z * ar.z + v.w * ar.w;
            sc += v.x * ac.x + v.y * ac.y + v.z * ac.z + v.w * ac.w;
        }
        int gr = m0 + row;
        if (gr < NN) {
            g_s1r[gr * 4 + hg] = sr;
            g_s1c[gr * 4 + hg] = sc;
        }
    }
}

// ---------------- GEMM2: Wh2 = h16 @ B2 [128x48, K=256, fp16 single-pass, 2 CTAs/SM, fused s2] ----------------
#define T2_A 0
#define T2_B 34816
#define T2_STAGE 49152
#define T2_BYTES (2 * T2_STAGE)

__global__ __launch_bounds__(256, 2) void k_gemm2(const float* __restrict__ aout) {
    extern __shared__ __align__(16) unsigned char smem[];
    uint32_t sbase = smem_u32(smem);
    int tid = threadIdx.x;
    int m0 = blockIdx.x * 128;

    #pragma unroll
    for (int c = 0; c < 2; c++) {
        uint32_t st = sbase + c * T2_STAGE;
        #pragma unroll
        for (int t = 0; t < 8; t++) {           // A: 2048 chunks (128 rows x 16)
            int idx = tid + t * 256;
            int r = idx >> 4, c16 = idx & 15;
            size_t so = ((size_t)(m0 + r) * 256 + c * 128 + c16 * 8) * 2;
            cpa16(st + T2_A + (uint32_t)(r * 136 + c16 * 8) * 2, (const unsigned char*)g_h16 + so);
        }
        #pragma unroll
        for (int t = 0; t < 3; t++) {           // B: 768 chunks (128 k-rows x 6)
            int idx = tid + t * 256;
            int kr = idx / 6, c6 = idx - kr * 6;
            size_t so = ((size_t)(c * 128 + kr) * 48 + c6 * 8) * 2;
            cpa16(st + T2_B + (uint32_t)(kr * 56 + c6 * 8) * 2, (const unsigned char*)g_B2f + so);
        }
        CP_COMMIT();
    }

    int wid = tid >> 5;                          // warp tile 16 x 48

    wmma::fragment<wmma::accumulator, 16, 16, 16, float> acc[3];
    #pragma unroll
    for (int j = 0; j < 3; j++) wmma::fill_fragment(acc[j], 0.f);

    CP_WAIT1();
    __syncthreads();

    #pragma unroll
    for (int c = 0; c < 2; c++) {
        const unsigned char* st = smem + c * T2_STAGE;
        const __half* A_ = (const __half*)(st + T2_A);
        const __half* B_ = (const __half*)(st + T2_B);
        #pragma unroll
        for (int k16 = 0; k16 < 8; k16++) {
            wmma::fragment<wmma::matrix_a, 16, 16, 16, __half, wmma::row_major> af;
            wmma::fragment<wmma::matrix_b, 16, 16, 16, __half, wmma::row_major> bfr[3];
            wmma::load_matrix_sync(af, A_ + (wid * 16) * 136 + k16 * 16, 136);
            #pragma unroll
            for (int j = 0; j < 3; j++)
                wmma::load_matrix_sync(bfr[j], B_ + (k16 * 16) * 56 + j * 16, 56);
            #pragma unroll
            for (int j = 0; j < 3; j++)
                wmma::mma_sync(acc[j], af, bfr[j], acc[j]);
        }
        if (c == 0) { CP_WAIT0(); __syncthreads(); }
    }

    __syncthreads();
    float* tile = (float*)smem;
    #pragma unroll
    for (int j = 0; j < 3; j++)
        wmma::store_matrix_sync(&tile[(wid * 16) * 56 + j * 16], acc[j], 56, wmma::mem_row_major);
    __syncthreads();

    #pragma unroll
    for (int t = 0; t < 6; t++) {               // fp16 Wh2 store
        int idx = tid + t * 256;
        int r = idx / 12, c4 = idx - r * 12;
        float4 v = *(const float4*)&tile[r * 56 + c4 * 4];
        __half2 p0 = __floats2half2_rn(v.x, v.y);
        __half2 p1 = __floats2half2_rn(v.z, v.w);
        uint2 o = make_uint2(*(uint32_t*)&p0, *(uint32_t*)&p1);
        *(uint2*)&g_Wh2h[(size_t)(m0 + r) * 48 + c4 * 4] = o;
    }
    if (tid < 128) {
        int row = tid;
        const float* rp = &tile[row * 56];
        float sr = 0.f, sc = 0.f;
        #pragma unroll
        for (int q = 0; q < 10; q++) {
            float4 v  = *(const float4*)&rp[q * 4];
            float4 ar = __ldg((const float4*)&aout[q * 4]);
            float4 ac = __ldg((const float4*)&aout[40 + q * 4]);
            sr += v.x * ar.x + v.y * ar.y + v.z * ar.z + v.w * ar.w;
            sc += v.x * ac.x + v.y * ac.y + v.z * ac.z + v.w * ac.w;
        }
        int gr = m0 + row;
        if (gr < NN) { g_s2r[gr] = sr; g_s2c[gr] = sc; }
    }
}

// ---------------- layer1 aggregation: HFMA2, 1/64-scaled half2 weights ----------------
__global__ __launch_bounds__(256) void k_gat1() {
    __shared__ __align__(16) __half2 sW[8][32][4];   // per warp, edge slot, head: (ex/64, ex/64)
    __shared__ int sJ[8][32];
    int w = threadIdx.x >> 5;
    int gw = (blockIdx.x * blockDim.x + threadIdx.x) >> 5;
    int lane = threadIdx.x & 31;
    if (gw >= NN) return;
    const float4 sr = *(const float4*)&g_s1r[gw * 4];
    int beg = g_off[gw], end = g_off[gw + 1];
    int hsel = lane >> 3;                         // head owned by this lane (8 cols each)

    __half2 accA0 = __float2half2_rn(0.f), accA1 = accA0, accA2 = accA0, accA3 = accA0;
    __half2 accB0 = accA0, accB1 = accA0, accB2 = accA0, accB3 = accA0;
    float d0 = 0.f, d1 = 0.f, d2 = 0.f, d3 = 0.f;

    for (int base = beg; base < end; base += 32) {
        int e = base + lane;
        int j = 0;
        float4 ex = make_float4(0.f, 0.f, 0.f, 0.f);
        if (e < end) {
            j = __ldg(&g_csr[e]);
            float4 s = __ldg((const float4*)&g_s1c[j * 4]);
            ex.x = __expf(lrelu(sr.x + s.x));
            ex.y = __expf(lrelu(sr.y + s.y));
            ex.z = __expf(lrelu(sr.z + s.z));
            ex.w = __expf(lrelu(sr.w + s.w));
            d0 += ex.x; d1 += ex.y; d2 += ex.z; d3 += ex.w;
        }
        {
            __half2 w0 = __floats2half2_rn(ex.x * 0.015625f, ex.x * 0.015625f);
            __half2 w1 = __floats2half2_rn(ex.y * 0.015625f, ex.y * 0.015625f);
            __half2 w2 = __floats2half2_rn(ex.z * 0.015625f, ex.z * 0.015625f);
            __half2 w3 = __floats2half2_rn(ex.w * 0.015625f, ex.w * 0.015625f);
            *(uint4*)&sW[w][lane][0] = make_uint4(*(uint32_t*)&w0, *(uint32_t*)&w1,
                                                  *(uint32_t*)&w2, *(uint32_t*)&w3);
        }
        sJ[w][lane] = j;
        __syncwarp();
        int cnt = min(32, end - base);
        for (int k = 0; k < cnt; k += 2) {
            {
                int jj = sJ[w][k];
                __half2 wt = sW[w][k][hsel];
                uint4 q = __ldg((const uint4*)&g_Wh1h[(size_t)jj * 256 + 8 * lane]);
                accA0 = __hfma2(wt, *(__half2*)&q.x, accA0);
                accA1 = __hfma2(wt, *(__half2*)&q.y, accA1);
                accA2 = __hfma2(wt, *(__half2*)&q.z, accA2);
                accA3 = __hfma2(wt, *(__half2*)&q.w, accA3);
            }
            if (k + 1 < cnt) {
                int jj = sJ[w][k + 1];
                __half2 wt = sW[w][k + 1][hsel];
                uint4 q = __ldg((const uint4*)&g_Wh1h[(size_t)jj * 256 + 8 * lane]);
                accB0 = __hfma2(wt, *(__half2*)&q.x, accB0);
                accB1 = __hfma2(wt, *(__half2*)&q.y, accB1);
                accB2 = __hfma2(wt, *(__half2*)&q.z, accB2);
                accB3 = __hfma2(wt, *(__half2*)&q.w, accB3);
            }
        }
        __syncwarp();
    }
    d0 = wsum(d0); d1 = wsum(d1); d2 = wsum(d2); d3 = wsum(d3);
    // inv includes the 64x rescale of the fp16 accumulators
    float inv = (hsel & 2) ? ((hsel & 1) ? 64.f / d3 : 64.f / d2)
                           : ((hsel & 1) ? 64.f / d1 : 64.f / d0);

    float2 fa0 = __half22float2(accA0), fb0 = __half22float2(accB0);
    float2 fa1 = __half22float2(accA1), fb1 = __half22float2(accB1);
    float2 fa2 = __half22float2(accA2), fb2 = __half22float2(accB2);
    float2 fa3 = __half22float2(accA3), fb3 = __half22float2(accB3);

    __half2 o0 = __floats2half2_rn(elu((fa0.x + fb0.x) * inv), elu((fa0.y + fb0.y) * inv));
    __half2 o1 = __floats2half2_rn(elu((fa1.x + fb1.x) * inv), elu((fa1.y + fb1.y) * inv));
    __half2 o2 = __floats2half2_rn(elu((fa2.x + fb2.x) * inv), elu((fa2.y + fb2.y) * inv));
    __half2 o3 = __floats2half2_rn(elu((fa3.x + fb3.x) * inv), elu((fa3.y + fb3.y) * inv));
    uint4 o = make_uint4(*(uint32_t*)&o0, *(uint32_t*)&o1,
                         *(uint32_t*)&o2, *(uint32_t*)&o3);
    *(uint4*)&g_h16[(size_t)gw * 256 + 8 * lane] = o;
}

// ---------------- layer2 attention + ELU + log_softmax ----------------
__global__ void k_gat2(float* __restrict__ out) {
    int gw = (blockIdx.x * blockDim.x + threadIdx.x) >> 5;
    int lane = threadIdx.x & 31;
    if (gw >= NN) return;
    float s2v = __ldg(&g_s2r[gw]);
    int beg = g_off[gw], end = g_off[gw + 1];
    int half = lane >> 4, sl = lane & 15;

    float4 acc = make_float4(0.f, 0.f, 0.f, 0.f);
    float den = 0.f;
    for (int base = beg; base < end; base += 32) {
        int e = base + lane;
        int j = 0; float ex = 0.f;
        if (e < end) {
            j = __ldg(&g_csr[e]);
            ex = __expf(lrelu(s2v + __ldg(&g_s2c[j])));
            den += ex;
        }
        int cnt = min(32, end - base);
        for (int k = 0; k < cnt; k += 2) {
            int kk = k + half;
            int src = (kk < cnt) ? kk : k;
            int   jj = __shfl_sync(0xffffffffu, j,  src);
            float w  = __shfl_sync(0xffffffffu, ex, src);
            if (kk >= cnt) w = 0.f;
            if (sl < 10) {
                uint2 q = __ldg((const uint2*)&g_Wh2h[(size_t)jj * 48 + 4 * sl]);
                float2 f0 = __half22float2(*(__half2*)&q.x);
                float2 f1 = __half22float2(*(__half2*)&q.y);
                acc.x += w * f0.x; acc.y += w * f0.y; acc.z += w * f1.x; acc.w += w * f1.y;
            }
        }
    }
    acc.x += __shfl_xor_sync(0xffffffffu, acc.x, 16);
    acc.y += __shfl_xor_sync(0xffffffffu, acc.y, 16);
    acc.z += __shfl_xor_sync(0xffffffffu, acc.z, 16);
    acc.w += __shfl_xor_sync(0xffffffffu, acc.w, 16);
    den = wsum(den);
    float inv = 1.f / den;
    bool valid = (lane < 10);
    float o0 = -1e30f, o1 = -1e30f, o2 = -1e30f, o3 = -1e30f;
    if (valid) {
        o0 = elu(acc.x * inv); o1 = elu(acc.y * inv);
        o2 = elu(acc.z * inv); o3 = elu(acc.w * inv);
    }
    float mm = wmax(fmaxf(fmaxf(o0, o1), fmaxf(o2, o3)));
    float se = 0.f;
    if (valid) se = __expf(o0 - mm) + __expf(o1 - mm) + __expf(o2 - mm) + __expf(o3 - mm);
    se = wsum(se);
    float L = mm + logf(se);
    if (valid)
        *(float4*)&out[(size_t)gw * NCLASS + 4 * lane] = make_float4(o0 - L, o1 - L, o2 - L, o3 - L);
}

// ---------------- launch ----------------
extern "C" void kernel_launch(void* const* d_in, const int* in_sizes, int n_in,
                              void* d_out, int out_size) {
    const float* x    = (const float*)d_in[0];
    const float* W    = (const float*)d_in[1];
    const float* a    = (const float*)d_in[2];
    const float* Wout = (const float*)d_in[3];
    const float* aout = (const float*)d_in[4];
    const int*   row  = (const int*)d_in[5];
    const int*   col  = (const int*)d_in[6];
    int E = in_sizes[5];
    float* out = (float*)d_out;

    static cudaStream_t s2 = nullptr;
    static cudaEvent_t evF = nullptr, evJ = nullptr;
    if (!s2) {
        cudaStreamCreateWithFlags(&s2, cudaStreamNonBlocking);
        cudaEventCreateWithFlags(&evF, cudaEventDisableTiming);
        cudaEventCreateWithFlags(&evJ, cudaEventDisableTiming);
        cudaFuncSetAttribute(k_gemm1, cudaFuncAttributeMaxDynamicSharedMemorySize, T1_BYTES);
        cudaFuncSetAttribute(k_gemm2, cudaFuncAttributeMaxDynamicSharedMemorySize, T2_BYTES);
    }

    // fork CSR chain immediately
    cudaEventRecord(evF, 0);
    cudaStreamWaitEvent(s2, evF, 0);
    k_zero <<<(NN + 255) / 256, 256, 0, s2>>>();
    k_count<<<(E + 255) / 256, 256, 0, s2>>>(row, E);

    k_prep<<<1280, 256>>>(x, W, Wout);
    k_gemm1<<<dim3(NTILE, 2), 256, T1_BYTES>>>(a);     // profiled slot

    k_scan1<<<NB1, SB, 0, s2>>>();
    k_scan2<<<1, 256, 0, s2>>>();
    k_scan3<<<NB1, SB, 0, s2>>>(E);
    k_fill <<<(E + 255) / 256, 256, 0, s2>>>(row, col, E);

    cudaEventRecord(evJ, s2);
    cudaStreamWaitEvent(0, evJ, 0);

    k_gat1<<<(NN + 7) / 8, 256>>>();
    k_gemm2<<<NTILE, 256, T2_BYTES>>>(aout);
    k_gat2<<<(NN + 7) / 8, 256>>>(out);
}